// round 15
// baseline (speedup 1.0000x reference)
#include <cuda_runtime.h>
#include <cuda_bf16.h>
#include <math.h>
#include <stdint.h>

#define NB 2
#define NL 2048
#define NLC 2048
#define NH 16
#define DMODEL 1024
#define NROWS (NB*NL)

typedef __nv_bfloat16 bf16;

// ---------------- scratch ----------------
__device__ bf16 g_xnb[NROWS*DMODEL];
__device__ bf16 g_xcb[NROWS*DMODEL];
__device__ bf16 g_wq [DMODEL*DMODEL];
__device__ bf16 g_wkv[2*DMODEL*DMODEL];
__device__ bf16 g_wout[DMODEL*DMODEL];
__device__ bf16 g_qpre[NROWS*DMODEL];
__device__ bf16 g_kvb [NROWS*2*DMODEL];
__device__ bf16 g_qb[NROWS*DMODEL];
__device__ bf16 g_kb[NROWS*DMODEL];
__device__ bf16 g_ob[NROWS*DMODEL];
__device__ float g_ftab[160];

// ---------------- PTX helpers ----------------
__device__ __forceinline__ uint32_t s2u(const void* p) {
    return (uint32_t)__cvta_generic_to_shared(p);
}
__device__ __forceinline__ void cp16(void* s, const void* g) {
    asm volatile("cp.async.cg.shared.global [%0], [%1], 16;\n" :: "r"(s2u(s)), "l"(g));
}
#define CP_COMMIT() asm volatile("cp.async.commit_group;\n")
#define CP_WAIT0()  asm volatile("cp.async.wait_group 0;\n")

__device__ __forceinline__ void ldmx4(unsigned* r, const void* p) {
    asm volatile("ldmatrix.sync.aligned.m8n8.x4.shared.b16 {%0,%1,%2,%3}, [%4];"
                 : "=r"(r[0]), "=r"(r[1]), "=r"(r[2]), "=r"(r[3]) : "r"(s2u(p)));
}
__device__ __forceinline__ void ldmx4t(unsigned* r, const void* p) {
    asm volatile("ldmatrix.sync.aligned.m8n8.x4.trans.shared.b16 {%0,%1,%2,%3}, [%4];"
                 : "=r"(r[0]), "=r"(r[1]), "=r"(r[2]), "=r"(r[3]) : "r"(s2u(p)));
}
__device__ __forceinline__ void mma16(float* d, const unsigned* a, const unsigned* b) {
    asm("mma.sync.aligned.m16n8k16.row.col.f32.bf16.bf16.f32 "
        "{%0,%1,%2,%3},{%4,%5,%6,%7},{%8,%9},{%0,%1,%2,%3};"
        : "+f"(d[0]), "+f"(d[1]), "+f"(d[2]), "+f"(d[3])
        : "r"(a[0]), "r"(a[1]), "r"(a[2]), "r"(a[3]), "r"(b[0]), "r"(b[1]));
}
__device__ __forceinline__ int swz(int row, int ch) {   // elem idx, 64-elem (128B) rows
    return row*64 + ((ch ^ (row & 7)) << 3);
}
__device__ __forceinline__ unsigned packbf(float a, float b) {
    __nv_bfloat162 h = __floats2bfloat162_rn(a, b);
    return *(unsigned*)&h;
}

// ---------------- RoPE freq table: fr[i] = pi * 10^(i/160) ----------------
__global__ void ftab_k() {
    int i = threadIdx.x;
    if (i < 160) g_ftab[i] = 3.14159265358979323846f * exp10f((float)i * (1.0f/160.0f));
}

// ---------------- fp32 -> bf16 convert (4x float4 per thread, MLP=4) --------------
__global__ __launch_bounds__(256) void f2b_k(const float* __restrict__ src,
                                             bf16* __restrict__ dst, int n4) {
    int i0 = blockIdx.x*1024 + threadIdx.x;
    float4 v[4];
    #pragma unroll
    for (int k = 0; k < 4; k++) v[k] = ((const float4*)src)[i0 + k*256];
    #pragma unroll
    for (int k = 0; k < 4; k++) {
        uint2 pk;
        pk.x = packbf(v[k].x, v[k].y);
        pk.y = packbf(v[k].z, v[k].w);
        ((uint2*)dst)[i0 + k*256] = pk;
    }
}

// ---------------- RMS norm: warp per row, MLP=8 ----------------
__global__ __launch_bounds__(256) void rmsnorm_k(const float* __restrict__ x,
                                                 const float* __restrict__ scale,
                                                 bf16* __restrict__ out) {
    const int w = threadIdx.x >> 5, lane = threadIdx.x & 31;
    const size_t row = blockIdx.x*8 + w;
    const float4* xr = (const float4*)(x + row*DMODEL);
    const float4* sc = (const float4*)scale;
    float4 v[8];
    #pragma unroll
    for (int i = 0; i < 8; i++) v[i] = xr[lane + i*32];
    float ss = 0.f;
    #pragma unroll
    for (int i = 0; i < 8; i++)
        ss += v[i].x*v[i].x + v[i].y*v[i].y + v[i].z*v[i].z + v[i].w*v[i].w;
    #pragma unroll
    for (int o = 16; o; o >>= 1) ss += __shfl_xor_sync(0xffffffffu, ss, o);
    float inv = rsqrtf(ss * (1.0f/DMODEL) + 1e-6f);
    uint2* op = (uint2*)(out + row*DMODEL);
    #pragma unroll
    for (int i = 0; i < 8; i++) {
        float4 s = sc[lane + i*32];
        uint2 pk;
        pk.x = packbf(v[i].x*s.x*inv, v[i].y*s.y*inv);
        pk.y = packbf(v[i].z*s.z*inv, v[i].w*s.w*inv);
        op[lane + i*32] = pk;
    }
}

// ---------------- bf16 mma GEMM: C[M,cols] = A[M,K]@B[rows,K]^T (+skip) -----------
// 128x128 block, BK=64, 2-stage cp.async, 8 warps, 2 CTAs/SM.
#define GEMM_SMEM (2*32768)

template<typename OutT, bool ADD>
__global__ __launch_bounds__(256, 2) void gemm_bf(const bf16* __restrict__ A,
                                                  const bf16* __restrict__ B,
                                                  const float* __restrict__ skip,
                                                  OutT* __restrict__ C,
                                                  int M, int K, int ldc) {
    extern __shared__ char sm[];
    const int bm = blockIdx.y*128, bn = blockIdx.x*128;
    const int tid = threadIdx.x, w = tid >> 5, lane = tid & 31;
    const int g = lane >> 2, t4 = lane & 3;
    const int part = lane >> 3, l7 = lane & 7;
    const int wm = (w >> 2)*64, wn = (w & 3)*32;

    float acc[4][4][4] = {};
    const int T = K >> 6;

    auto load_tile = [&](int kt) {
        int st = kt & 1;
        char* As = sm + st*32768;
        char* Bs = As + 16384;
        int k0 = kt << 6;
        #pragma unroll
        for (int i = 0; i < 4; i++) {
            int c = tid + i*256, r = c >> 3, ch = c & 7;
            cp16(As + r*128 + ((ch ^ (r & 7)) << 4), A + (size_t)(bm + r)*K + k0 + ch*8);
            cp16(Bs + r*128 + ((ch ^ (r & 7)) << 4), B + (size_t)(bn + r)*K + k0 + ch*8);
        }
    };

    load_tile(0); CP_COMMIT();

    for (int kt = 0; kt < T; kt++) {
        CP_WAIT0();
        __syncthreads();
        if (kt + 1 < T) { load_tile(kt + 1); CP_COMMIT(); }

        int st = kt & 1;
        const bf16* As = (const bf16*)(sm + st*32768);
        const bf16* Bs = (const bf16*)(sm + st*32768 + 16384);
        #pragma unroll
        for (int ks = 0; ks < 4; ks++) {
            unsigned af[4][4], bfr[4][2];
            #pragma unroll
            for (int mt = 0; mt < 4; mt++) {
                int row = wm + mt*16 + (part & 1)*8 + l7;
                int ch  = ks*2 + (part >> 1);
                ldmx4(af[mt], &As[swz(row, ch)]);
            }
            #pragma unroll
            for (int p = 0; p < 2; p++) {
                int row = wn + p*16 + (part >> 1)*8 + l7;
                int ch  = ks*2 + (part & 1);
                unsigned r4[4];
                ldmx4(r4, &Bs[swz(row, ch)]);
                bfr[2*p][0] = r4[0]; bfr[2*p][1] = r4[1];
                bfr[2*p+1][0] = r4[2]; bfr[2*p+1][1] = r4[3];
            }
            #pragma unroll
            for (int mt = 0; mt < 4; mt++)
                #pragma unroll
                for (int nt = 0; nt < 4; nt++)
                    mma16(acc[mt][nt], af[mt], bfr[nt]);
        }
        __syncthreads();
    }

    #pragma unroll
    for (int mt = 0; mt < 4; mt++) {
        size_t r0 = bm + wm + mt*16 + g, r1 = r0 + 8;
        #pragma unroll
        for (int nt = 0; nt < 4; nt++) {
            size_t cc = bn + wn + nt*8 + 2*t4;
            float2 v0 = make_float2(acc[mt][nt][0], acc[mt][nt][1]);
            float2 v1 = make_float2(acc[mt][nt][2], acc[mt][nt][3]);
            if (ADD) {
                float2 s0 = *(const float2*)&skip[r0*ldc + cc];
                float2 s1 = *(const float2*)&skip[r1*ldc + cc];
                v0.x += s0.x; v0.y += s0.y; v1.x += s1.x; v1.y += s1.y;
            }
            if (sizeof(OutT) == 4) {
                *(float2*)&((float*)C)[r0*ldc + cc] = v0;
                *(float2*)&((float*)C)[r1*ldc + cc] = v1;
            } else {
                *(unsigned*)&((bf16*)C)[r0*ldc + cc] = packbf(v0.x, v0.y);
                *(unsigned*)&((bf16*)C)[r1*ldc + cc] = packbf(v1.x, v1.y);
            }
        }
    }
}

// ---------------- cosine scale + 3-axis RoPE: warp-per-vector, freq table ---------
__global__ __launch_bounds__(256) void qkprep_k(const bf16* __restrict__ src, int sstride,
                                                const float* __restrict__ pos,
                                                const float* __restrict__ head_scale,
                                                bf16* __restrict__ dst) {
    const int warp = threadIdx.x >> 5, lane = threadIdx.x & 31;
    const int gv0 = (blockIdx.x*8 + warp)*2;
    const int srcl = (lane < 15) ? lane + 15 : lane - 15;

    #pragma unroll
    for (int vv = 0; vv < 2; vv++) {
        int gv = gv0 + vv;
        int row = gv >> 4, h = gv & 15;
        unsigned u = ((const unsigned*)(src + (size_t)row*sstride + h*64))[lane];
        __nv_bfloat162 bb = *(__nv_bfloat162*)&u;
        float f0 = __bfloat162float(bb.x), f1 = __bfloat162float(bb.y);
        float ss = f0*f0 + f1*f1;
        #pragma unroll
        for (int o = 16; o; o >>= 1) ss += __shfl_xor_sync(0xffffffffu, ss, o);
        float cs = sqrtf(head_scale[h]) * rsqrtf(ss + 1e-6f);
        float p0 = __shfl_sync(0xffffffffu, f0, srcl);
        float p1 = __shfl_sync(0xffffffffu, f1, srcl);
        float out0, out1;
        if (lane < 30) {
            int i0 = (lane < 15) ? 2*lane : 2*lane - 30;   // i in [0,30), even
            int a0 = i0/10, j0 = i0 - a0*10;
            int i1 = i0 + 1;
            int a1 = i1/10, j1 = i1 - a1*10;
            float fr0 = g_ftab[j0*16 + h];
            float fr1 = g_ftab[j1*16 + h];
            float th0 = pos[(size_t)row*3 + a0]*fr0;
            float th1 = pos[(size_t)row*3 + a1]*fr1;
            float s0, c0, s1, c1;
            __sincosf(th0, &s0, &c0);
            __sincosf(th1, &s1, &c1);
            if (lane < 15) { out0 = cs*(f0*c0 - p0*s0); out1 = cs*(f1*c1 - p1*s1); }
            else           { out0 = cs*(f0*c0 + p0*s0); out1 = cs*(f1*c1 + p1*s1); }
        } else {
            out0 = cs*f0; out1 = cs*f1;
        }
        ((unsigned*)(dst + (size_t)row*DMODEL + h*64))[lane] = packbf(out0, out1);
    }
}

// ---------------- flash attention: 2-stage, 2 CTAs/SM, single launch z=2 ----------
#define ATT_SMEM (16384 + 2*32768)   // Qs + 2 x (K 16KB + V 16KB) = 80KB

__global__ __launch_bounds__(256, 2) void attn_bf16(const bf16* __restrict__ Q,
                                                    const bf16* __restrict__ Kb,
                                                    const bf16* __restrict__ KVb,
                                                    bf16* __restrict__ O) {
    extern __shared__ char sm[];
    bf16* Qs = (bf16*)sm;
    const int b = blockIdx.z, h = blockIdx.y, m0 = blockIdx.x*128;
    const int tid = threadIdx.x, w = tid >> 5, lane = tid & 31;
    const int g = lane >> 2, t4 = lane & 3;
    const int part = lane >> 3, l7 = lane & 7;

    auto load_kv = [&](int kt) {
        int st = kt & 1;
        bf16* Ks = (bf16*)(sm + 16384 + st*32768);
        bf16* Vs = Ks + 8192;
        int n0 = kt << 7;
        #pragma unroll
        for (int i = 0; i < 4; i++) {
            int c = tid + i*256, row = c >> 3, ch = c & 7;
            cp16(&Ks[swz(row, ch)],
                 Kb + ((size_t)(b*NLC + n0 + row)*NH + h)*64 + ch*8);
            cp16(&Vs[swz(row, ch)],
                 KVb + (size_t)(b*NLC + n0 + row)*(2*DMODEL) + DMODEL + h*64 + ch*8);
        }
    };

    #pragma unroll
    for (int i = 0; i < 4; i++) {
        int c = tid + i*256, row = c >> 3, ch = c & 7;
        cp16(&Qs[swz(row, ch)], Q + ((size_t)(b*NL + m0 + row)*NH + h)*64 + ch*8);
    }
    load_kv(0);
    CP_COMMIT();

    CP_WAIT0();          // Q + KV0 ready
    __syncthreads();
    unsigned qf[4][4];
    #pragma unroll
    for (int ks = 0; ks < 4; ks++) {
        int row = 16*w + (part & 1)*8 + l7;
        int ch  = ks*2 + (part >> 1);
        ldmx4(qf[ks], &Qs[swz(row, ch)]);
    }

    float o_acc[8][4] = {};
    float rs0 = 0.f, rs1 = 0.f;

    const int T = NLC/128;
    for (int kt = 0; kt < T; kt++) {
        if (kt > 0) {
            CP_WAIT0();
            __syncthreads();
        }
        if (kt + 1 < T) { load_kv(kt + 1); CP_COMMIT(); }

        int st = kt & 1;
        const bf16* Ks = (const bf16*)(sm + 16384 + st*32768);
        const bf16* Vs = Ks + 8192;

        #pragma unroll
        for (int half = 0; half < 2; half++) {
            const int koff = half*64;
            float s[8][4] = {};
            #pragma unroll
            for (int ks = 0; ks < 4; ks++) {
                #pragma unroll
                for (int p = 0; p < 4; p++) {
                    int row = koff + p*16 + (part >> 1)*8 + l7;
                    int ch  = ks*2 + (part & 1);
                    unsigned r4[4];
                    ldmx4(r4, &Ks[swz(row, ch)]);
                    mma16(s[2*p],   qf[ks], r4);
                    mma16(s[2*p+1], qf[ks], r4 + 2);
                }
            }
            #pragma unroll
            for (int nt = 0; nt < 8; nt++) {
                s[nt][0] = __expf(s[nt][0] - 10.0f);
                s[nt][1] = __expf(s[nt][1] - 10.0f);
                s[nt][2] = __expf(s[nt][2] - 10.0f);
                s[nt][3] = __expf(s[nt][3] - 10.0f);
                rs0 += s[nt][0] + s[nt][1];
                rs1 += s[nt][2] + s[nt][3];
            }
            #pragma unroll
            for (int ks = 0; ks < 4; ks++) {
                unsigned ap[4];
                ap[0] = packbf(s[2*ks][0],   s[2*ks][1]);
                ap[1] = packbf(s[2*ks][2],   s[2*ks][3]);
                ap[2] = packbf(s[2*ks+1][0], s[2*ks+1][1]);
                ap[3] = packbf(s[2*ks+1][2], s[2*ks+1][3]);
                #pragma unroll
                for (int p = 0; p < 4; p++) {
                    int row = koff + ks*16 + (part & 1)*8 + l7;
                    int ch  = p*2 + (part >> 1);
                    unsigned r4[4];
                    ldmx4t(r4, &Vs[swz(row, ch)]);
                    mma16(o_acc[2*p],   ap, r4);
                    mma16(o_acc[2*p+1], ap, r4 + 2);
                }
            }
        }
        __syncthreads();
    }

    #pragma unroll
    for (int off = 1; off <= 2; off <<= 1) {
        rs0 += __shfl_xor_sync(0xffffffffu, rs0, off);
        rs1 += __shfl_xor_sync(0xffffffffu, rs1, off);
    }
    float inv0 = 1.f / rs0, inv1 = 1.f / rs1;
    size_t r0 = m0 + 16*w + g, r1 = r0 + 8;
    #pragma unroll
    for (int nt = 0; nt < 8; nt++) {
        size_t cc = nt*8 + 2*t4;
        *(unsigned*)&O[((size_t)(b*NL + r0)*NH + h)*64 + cc] =
            packbf(o_acc[nt][0]*inv0, o_acc[nt][1]*inv0);
        *(unsigned*)&O[((size_t)(b*NL + r1)*NH + h)*64 + cc] =
            packbf(o_acc[nt][2]*inv1, o_acc[nt][3]*inv1);
    }
}

// ---------------- launcher: round-10 fork-join graph (proven) ----------------
static cudaStream_t g_s1 = nullptr, g_s2 = nullptr;
static cudaEvent_t  g_ev[7];

extern "C" void kernel_launch(void* const* d_in, const int* in_sizes, int n_in,
                              void* d_out, int out_size) {
    const float* x      = (const float*)d_in[0];
    const float* pos    = (const float*)d_in[1];
    const float* x_cross= (const float*)d_in[2];
    const float* posc   = (const float*)d_in[3];
    const float* nscale = (const float*)d_in[4];
    const float* ncscale= (const float*)d_in[5];
    const float* q_w    = (const float*)d_in[6];
    const float* kv_w   = (const float*)d_in[7];
    const float* hscale = (const float*)d_in[8];
    const float* out_w  = (const float*)d_in[9];
    float* out = (float*)d_out;

    if (!g_s1) {
        cudaStreamCreateWithFlags(&g_s1, cudaStreamNonBlocking);
        cudaStreamCreateWithFlags(&g_s2, cudaStreamNonBlocking);
        for (int i = 0; i < 7; i++)
            cudaEventCreateWithFlags(&g_ev[i], cudaEventDisableTiming);
    }
    cudaEvent_t eFork = g_ev[0], eFtab = g_ev[1], eXcb = g_ev[2], eWkv = g_ev[3],
                eWout = g_ev[4], eQ = g_ev[5], eV = g_ev[6];

    bf16 *xnb, *xcb, *wq, *wkv, *wout, *qpre, *kvb, *qb, *kb, *ob;
    cudaGetSymbolAddress((void**)&xnb, g_xnb);
    cudaGetSymbolAddress((void**)&xcb, g_xcb);
    cudaGetSymbolAddress((void**)&wq,  g_wq);
    cudaGetSymbolAddress((void**)&wkv, g_wkv);
    cudaGetSymbolAddress((void**)&wout,g_wout);
    cudaGetSymbolAddress((void**)&qpre,g_qpre);
    cudaGetSymbolAddress((void**)&kvb, g_kvb);
    cudaGetSymbolAddress((void**)&qb,  g_qb);
    cudaGetSymbolAddress((void**)&kb,  g_kb);
    cudaGetSymbolAddress((void**)&ob,  g_ob);

    cudaFuncSetAttribute(gemm_bf<bf16,false>, cudaFuncAttributeMaxDynamicSharedMemorySize, GEMM_SMEM);
    cudaFuncSetAttribute(gemm_bf<float,true>, cudaFuncAttributeMaxDynamicSharedMemorySize, GEMM_SMEM);
    cudaFuncSetAttribute(attn_bf16, cudaFuncAttributeMaxDynamicSharedMemorySize, ATT_SMEM);

    const dim3 gFull(8, NROWS/128);

    // fork
    cudaEventRecord(eFork, 0);
    cudaStreamWaitEvent(g_s1, eFork, 0);
    cudaStreamWaitEvent(g_s2, eFork, 0);

    // ---- s2: kv-weight convert FIRST (gates critical-path K-proj), then wout ----
    f2b_k<<<2*DMODEL*DMODEL/4/1024, 256, 0, g_s2>>>(kv_w, wkv, 2*DMODEL*DMODEL/4);
    cudaEventRecord(eWkv, g_s2);
    f2b_k<<<DMODEL*DMODEL/4/1024, 256, 0, g_s2>>>(out_w, wout, DMODEL*DMODEL/4);
    cudaEventRecord(eWout, g_s2);

    // ---- s1: ftab + q-side chain ----
    ftab_k<<<1, 160, 0, g_s1>>>();
    cudaEventRecord(eFtab, g_s1);
    f2b_k<<<DMODEL*DMODEL/4/1024, 256, 0, g_s1>>>(q_w, wq, DMODEL*DMODEL/4);
    rmsnorm_k<<<NROWS/8, 256, 0, g_s1>>>(x, nscale, xnb);
    gemm_bf<bf16,false><<<gFull, 256, GEMM_SMEM, g_s1>>>(
        xnb, wq, nullptr, qpre, NROWS, DMODEL, DMODEL);
    qkprep_k<<<NROWS*NH/16, 256, 0, g_s1>>>(qpre, DMODEL, pos, hscale, qb);
    cudaEventRecord(eQ, g_s1);

    // ---- s0 (critical path): rms_xc -> K-proj -> K-prep -> attn -> out-proj ----
    rmsnorm_k<<<NROWS/8, 256>>>(x_cross, ncscale, xcb);
    cudaEventRecord(eXcb, 0);

    // V projection on s2 (needs wkv + xcb), overlaps with K chain on s0
    cudaStreamWaitEvent(g_s2, eXcb, 0);
    gemm_bf<bf16,false><<<gFull, 256, GEMM_SMEM, g_s2>>>(
        xcb, wkv + DMODEL*DMODEL, nullptr, kvb + DMODEL, NROWS, DMODEL, 2*DMODEL);
    cudaEventRecord(eV, g_s2);

    // K projection + prep on s0
    cudaStreamWaitEvent(0, eWkv, 0);
    gemm_bf<bf16,false><<<gFull, 256, GEMM_SMEM>>>(
        xcb, wkv, nullptr, kvb, NROWS, DMODEL, 2*DMODEL);
    cudaStreamWaitEvent(0, eFtab, 0);
    qkprep_k<<<NROWS*NH/16, 256>>>(kvb, 2*DMODEL, posc, hscale, kb);

    cudaStreamWaitEvent(0, eQ, 0);   // join q chain
    cudaStreamWaitEvent(0, eV, 0);   // join V projection
    attn_bf16<<<dim3(NL/128, NH, NB), 256, ATT_SMEM>>>(qb, kb, kvb, ob);

    cudaStreamWaitEvent(0, eWout, 0); // join wout convert
    gemm_bf<float,true><<<gFull, 256, GEMM_SMEM>>>(
        ob, wout, x, out, NROWS, DMODEL, DMODEL);
}

// round 16
// speedup vs baseline: 1.0345x; 1.0345x over previous
#include <cuda_runtime.h>
#include <cuda_bf16.h>
#include <math.h>
#include <stdint.h>

#define NB 2
#define NL 2048
#define NLC 2048
#define NH 16
#define DMODEL 1024
#define NROWS (NB*NL)

typedef __nv_bfloat16 bf16;

// ---------------- scratch ----------------
__device__ bf16 g_xnb[NROWS*DMODEL];
__device__ bf16 g_xcb[NROWS*DMODEL];
__device__ bf16 g_wq [DMODEL*DMODEL];
__device__ bf16 g_wkv[2*DMODEL*DMODEL];
__device__ bf16 g_wout[DMODEL*DMODEL];
__device__ bf16 g_qpre[NROWS*DMODEL];
__device__ bf16 g_kvb [NROWS*2*DMODEL];
__device__ bf16 g_qb[NROWS*DMODEL];
__device__ bf16 g_kb[NROWS*DMODEL];
__device__ bf16 g_ob[NROWS*DMODEL];
__device__ float g_ftab[160];

// ---------------- PTX helpers ----------------
__device__ __forceinline__ uint32_t s2u(const void* p) {
    return (uint32_t)__cvta_generic_to_shared(p);
}
__device__ __forceinline__ void cp16(void* s, const void* g) {
    asm volatile("cp.async.cg.shared.global [%0], [%1], 16;\n" :: "r"(s2u(s)), "l"(g));
}
#define CP_COMMIT() asm volatile("cp.async.commit_group;\n")
#define CP_WAIT0()  asm volatile("cp.async.wait_group 0;\n")

__device__ __forceinline__ void ldmx4(unsigned* r, const void* p) {
    asm volatile("ldmatrix.sync.aligned.m8n8.x4.shared.b16 {%0,%1,%2,%3}, [%4];"
                 : "=r"(r[0]), "=r"(r[1]), "=r"(r[2]), "=r"(r[3]) : "r"(s2u(p)));
}
__device__ __forceinline__ void ldmx4t(unsigned* r, const void* p) {
    asm volatile("ldmatrix.sync.aligned.m8n8.x4.trans.shared.b16 {%0,%1,%2,%3}, [%4];"
                 : "=r"(r[0]), "=r"(r[1]), "=r"(r[2]), "=r"(r[3]) : "r"(s2u(p)));
}
__device__ __forceinline__ void mma16(float* d, const unsigned* a, const unsigned* b) {
    asm("mma.sync.aligned.m16n8k16.row.col.f32.bf16.bf16.f32 "
        "{%0,%1,%2,%3},{%4,%5,%6,%7},{%8,%9},{%0,%1,%2,%3};"
        : "+f"(d[0]), "+f"(d[1]), "+f"(d[2]), "+f"(d[3])
        : "r"(a[0]), "r"(a[1]), "r"(a[2]), "r"(a[3]), "r"(b[0]), "r"(b[1]));
}
__device__ __forceinline__ int swz(int row, int ch) {   // elem idx, 64-elem (128B) rows
    return row*64 + ((ch ^ (row & 7)) << 3);
}
__device__ __forceinline__ unsigned packbf(float a, float b) {
    __nv_bfloat162 h = __floats2bfloat162_rn(a, b);
    return *(unsigned*)&h;
}

// ---------------- RoPE freq table: fr[i] = pi * 10^(i/160) ----------------
__global__ void ftab_k() {
    int i = threadIdx.x;
    if (i < 160) g_ftab[i] = 3.14159265358979323846f * exp10f((float)i * (1.0f/160.0f));
}

// ---------------- fp32 -> bf16 convert (round-10 simple version) ----------------
__global__ __launch_bounds__(256) void f2b_k(const float* __restrict__ src,
                                             bf16* __restrict__ dst, int n4) {
    int i = blockIdx.x*256 + threadIdx.x;
    if (i >= n4) return;
    float4 v = ((const float4*)src)[i];
    ((__nv_bfloat162*)dst)[2*i]   = __floats2bfloat162_rn(v.x, v.y);
    ((__nv_bfloat162*)dst)[2*i+1] = __floats2bfloat162_rn(v.z, v.w);
}

// ---------------- RMS norm: warp per row, MLP=8 ----------------
__global__ __launch_bounds__(256) void rmsnorm_k(const float* __restrict__ x,
                                                 const float* __restrict__ scale,
                                                 bf16* __restrict__ out) {
    const int w = threadIdx.x >> 5, lane = threadIdx.x & 31;
    const size_t row = blockIdx.x*8 + w;
    const float4* xr = (const float4*)(x + row*DMODEL);
    const float4* sc = (const float4*)scale;
    float4 v[8];
    #pragma unroll
    for (int i = 0; i < 8; i++) v[i] = xr[lane + i*32];
    float ss = 0.f;
    #pragma unroll
    for (int i = 0; i < 8; i++)
        ss += v[i].x*v[i].x + v[i].y*v[i].y + v[i].z*v[i].z + v[i].w*v[i].w;
    #pragma unroll
    for (int o = 16; o; o >>= 1) ss += __shfl_xor_sync(0xffffffffu, ss, o);
    float inv = rsqrtf(ss * (1.0f/DMODEL) + 1e-6f);
    uint2* op = (uint2*)(out + row*DMODEL);
    #pragma unroll
    for (int i = 0; i < 8; i++) {
        float4 s = sc[lane + i*32];
        uint2 pk;
        pk.x = packbf(v[i].x*s.x*inv, v[i].y*s.y*inv);
        pk.y = packbf(v[i].z*s.z*inv, v[i].w*s.w*inv);
        op[lane + i*32] = pk;
    }
}

// ---------------- bf16 mma GEMM: C[M,cols] = A[M,K]@B[rows,K]^T (+skip) -----------
// 128x128 block, BK=64, 2-stage cp.async, 8 warps, 2 CTAs/SM.
#define GEMM_SMEM (2*32768)

template<typename OutT, bool ADD>
__global__ __launch_bounds__(256, 2) void gemm_bf(const bf16* __restrict__ A,
                                                  const bf16* __restrict__ B,
                                                  const float* __restrict__ skip,
                                                  OutT* __restrict__ C,
                                                  int M, int K, int ldc) {
    extern __shared__ char sm[];
    const int bm = blockIdx.y*128, bn = blockIdx.x*128;
    const int tid = threadIdx.x, w = tid >> 5, lane = tid & 31;
    const int g = lane >> 2, t4 = lane & 3;
    const int part = lane >> 3, l7 = lane & 7;
    const int wm = (w >> 2)*64, wn = (w & 3)*32;

    float acc[4][4][4] = {};
    const int T = K >> 6;

    auto load_tile = [&](int kt) {
        int st = kt & 1;
        char* As = sm + st*32768;
        char* Bs = As + 16384;
        int k0 = kt << 6;
        #pragma unroll
        for (int i = 0; i < 4; i++) {
            int c = tid + i*256, r = c >> 3, ch = c & 7;
            cp16(As + r*128 + ((ch ^ (r & 7)) << 4), A + (size_t)(bm + r)*K + k0 + ch*8);
            cp16(Bs + r*128 + ((ch ^ (r & 7)) << 4), B + (size_t)(bn + r)*K + k0 + ch*8);
        }
    };

    load_tile(0); CP_COMMIT();

    for (int kt = 0; kt < T; kt++) {
        CP_WAIT0();
        __syncthreads();
        if (kt + 1 < T) { load_tile(kt + 1); CP_COMMIT(); }

        int st = kt & 1;
        const bf16* As = (const bf16*)(sm + st*32768);
        const bf16* Bs = (const bf16*)(sm + st*32768 + 16384);
        #pragma unroll
        for (int ks = 0; ks < 4; ks++) {
            unsigned af[4][4], bfr[4][2];
            #pragma unroll
            for (int mt = 0; mt < 4; mt++) {
                int row = wm + mt*16 + (part & 1)*8 + l7;
                int ch  = ks*2 + (part >> 1);
                ldmx4(af[mt], &As[swz(row, ch)]);
            }
            #pragma unroll
            for (int p = 0; p < 2; p++) {
                int row = wn + p*16 + (part >> 1)*8 + l7;
                int ch  = ks*2 + (part & 1);
                unsigned r4[4];
                ldmx4(r4, &Bs[swz(row, ch)]);
                bfr[2*p][0] = r4[0]; bfr[2*p][1] = r4[1];
                bfr[2*p+1][0] = r4[2]; bfr[2*p+1][1] = r4[3];
            }
            #pragma unroll
            for (int mt = 0; mt < 4; mt++)
                #pragma unroll
                for (int nt = 0; nt < 4; nt++)
                    mma16(acc[mt][nt], af[mt], bfr[nt]);
        }
        __syncthreads();
    }

    #pragma unroll
    for (int mt = 0; mt < 4; mt++) {
        size_t r0 = bm + wm + mt*16 + g, r1 = r0 + 8;
        #pragma unroll
        for (int nt = 0; nt < 4; nt++) {
            size_t cc = bn + wn + nt*8 + 2*t4;
            float2 v0 = make_float2(acc[mt][nt][0], acc[mt][nt][1]);
            float2 v1 = make_float2(acc[mt][nt][2], acc[mt][nt][3]);
            if (ADD) {
                float2 s0 = *(const float2*)&skip[r0*ldc + cc];
                float2 s1 = *(const float2*)&skip[r1*ldc + cc];
                v0.x += s0.x; v0.y += s0.y; v1.x += s1.x; v1.y += s1.y;
            }
            if (sizeof(OutT) == 4) {
                *(float2*)&((float*)C)[r0*ldc + cc] = v0;
                *(float2*)&((float*)C)[r1*ldc + cc] = v1;
            } else {
                *(unsigned*)&((bf16*)C)[r0*ldc + cc] = packbf(v0.x, v0.y);
                *(unsigned*)&((bf16*)C)[r1*ldc + cc] = packbf(v1.x, v1.y);
            }
        }
    }
}

// ---------------- cosine scale + 3-axis RoPE: warp-per-vector, freq table ---------
__global__ __launch_bounds__(256) void qkprep_k(const bf16* __restrict__ src, int sstride,
                                                const float* __restrict__ pos,
                                                const float* __restrict__ head_scale,
                                                bf16* __restrict__ dst) {
    const int warp = threadIdx.x >> 5, lane = threadIdx.x & 31;
    const int gv0 = (blockIdx.x*8 + warp)*2;
    const int srcl = (lane < 15) ? lane + 15 : lane - 15;

    #pragma unroll
    for (int vv = 0; vv < 2; vv++) {
        int gv = gv0 + vv;
        int row = gv >> 4, h = gv & 15;
        unsigned u = ((const unsigned*)(src + (size_t)row*sstride + h*64))[lane];
        __nv_bfloat162 bb = *(__nv_bfloat162*)&u;
        float f0 = __bfloat162float(bb.x), f1 = __bfloat162float(bb.y);
        float ss = f0*f0 + f1*f1;
        #pragma unroll
        for (int o = 16; o; o >>= 1) ss += __shfl_xor_sync(0xffffffffu, ss, o);
        float cs = sqrtf(head_scale[h]) * rsqrtf(ss + 1e-6f);
        float p0 = __shfl_sync(0xffffffffu, f0, srcl);
        float p1 = __shfl_sync(0xffffffffu, f1, srcl);
        float out0, out1;
        if (lane < 30) {
            int i0 = (lane < 15) ? 2*lane : 2*lane - 30;   // i in [0,30), even
            int a0 = i0/10, j0 = i0 - a0*10;
            int i1 = i0 + 1;
            int a1 = i1/10, j1 = i1 - a1*10;
            float fr0 = g_ftab[j0*16 + h];
            float fr1 = g_ftab[j1*16 + h];
            float th0 = pos[(size_t)row*3 + a0]*fr0;
            float th1 = pos[(size_t)row*3 + a1]*fr1;
            float s0, c0, s1, c1;
            __sincosf(th0, &s0, &c0);
            __sincosf(th1, &s1, &c1);
            if (lane < 15) { out0 = cs*(f0*c0 - p0*s0); out1 = cs*(f1*c1 - p1*s1); }
            else           { out0 = cs*(f0*c0 + p0*s0); out1 = cs*(f1*c1 + p1*s1); }
        } else {
            out0 = cs*f0; out1 = cs*f1;
        }
        ((unsigned*)(dst + (size_t)row*DMODEL + h*64))[lane] = packbf(out0, out1);
    }
}

// ---------------- flash attention: 2-stage, 2 CTAs/SM, single launch z=2 ----------
#define ATT_SMEM (16384 + 2*32768)   // Qs + 2 x (K 16KB + V 16KB) = 80KB

__global__ __launch_bounds__(256, 2) void attn_bf16(const bf16* __restrict__ Q,
                                                    const bf16* __restrict__ Kb,
                                                    const bf16* __restrict__ KVb,
                                                    bf16* __restrict__ O) {
    extern __shared__ char sm[];
    bf16* Qs = (bf16*)sm;
    const int b = blockIdx.z, h = blockIdx.y, m0 = blockIdx.x*128;
    const int tid = threadIdx.x, w = tid >> 5, lane = tid & 31;
    const int g = lane >> 2, t4 = lane & 3;
    const int part = lane >> 3, l7 = lane & 7;

    auto load_kv = [&](int kt) {
        int st = kt & 1;
        bf16* Ks = (bf16*)(sm + 16384 + st*32768);
        bf16* Vs = Ks + 8192;
        int n0 = kt << 7;
        #pragma unroll
        for (int i = 0; i < 4; i++) {
            int c = tid + i*256, row = c >> 3, ch = c & 7;
            cp16(&Ks[swz(row, ch)],
                 Kb + ((size_t)(b*NLC + n0 + row)*NH + h)*64 + ch*8);
            cp16(&Vs[swz(row, ch)],
                 KVb + (size_t)(b*NLC + n0 + row)*(2*DMODEL) + DMODEL + h*64 + ch*8);
        }
    };

    #pragma unroll
    for (int i = 0; i < 4; i++) {
        int c = tid + i*256, row = c >> 3, ch = c & 7;
        cp16(&Qs[swz(row, ch)], Q + ((size_t)(b*NL + m0 + row)*NH + h)*64 + ch*8);
    }
    load_kv(0);
    CP_COMMIT();

    CP_WAIT0();          // Q + KV0 ready
    __syncthreads();
    unsigned qf[4][4];
    #pragma unroll
    for (int ks = 0; ks < 4; ks++) {
        int row = 16*w + (part & 1)*8 + l7;
        int ch  = ks*2 + (part >> 1);
        ldmx4(qf[ks], &Qs[swz(row, ch)]);
    }

    float o_acc[8][4] = {};
    float rs0 = 0.f, rs1 = 0.f;

    const int T = NLC/128;
    for (int kt = 0; kt < T; kt++) {
        if (kt > 0) {
            CP_WAIT0();
            __syncthreads();
        }
        if (kt + 1 < T) { load_kv(kt + 1); CP_COMMIT(); }

        int st = kt & 1;
        const bf16* Ks = (const bf16*)(sm + 16384 + st*32768);
        const bf16* Vs = Ks + 8192;

        #pragma unroll
        for (int half = 0; half < 2; half++) {
            const int koff = half*64;
            float s[8][4] = {};
            #pragma unroll
            for (int ks = 0; ks < 4; ks++) {
                #pragma unroll
                for (int p = 0; p < 4; p++) {
                    int row = koff + p*16 + (part >> 1)*8 + l7;
                    int ch  = ks*2 + (part & 1);
                    unsigned r4[4];
                    ldmx4(r4, &Ks[swz(row, ch)]);
                    mma16(s[2*p],   qf[ks], r4);
                    mma16(s[2*p+1], qf[ks], r4 + 2);
                }
            }
            #pragma unroll
            for (int nt = 0; nt < 8; nt++) {
                s[nt][0] = __expf(s[nt][0] - 10.0f);
                s[nt][1] = __expf(s[nt][1] - 10.0f);
                s[nt][2] = __expf(s[nt][2] - 10.0f);
                s[nt][3] = __expf(s[nt][3] - 10.0f);
                rs0 += s[nt][0] + s[nt][1];
                rs1 += s[nt][2] + s[nt][3];
            }
            #pragma unroll
            for (int ks = 0; ks < 4; ks++) {
                unsigned ap[4];
                ap[0] = packbf(s[2*ks][0],   s[2*ks][1]);
                ap[1] = packbf(s[2*ks][2],   s[2*ks][3]);
                ap[2] = packbf(s[2*ks+1][0], s[2*ks+1][1]);
                ap[3] = packbf(s[2*ks+1][2], s[2*ks+1][3]);
                #pragma unroll
                for (int p = 0; p < 4; p++) {
                    int row = koff + ks*16 + (part & 1)*8 + l7;
                    int ch  = p*2 + (part >> 1);
                    unsigned r4[4];
                    ldmx4t(r4, &Vs[swz(row, ch)]);
                    mma16(o_acc[2*p],   ap, r4);
                    mma16(o_acc[2*p+1], ap, r4 + 2);
                }
            }
        }
        __syncthreads();
    }

    #pragma unroll
    for (int off = 1; off <= 2; off <<= 1) {
        rs0 += __shfl_xor_sync(0xffffffffu, rs0, off);
        rs1 += __shfl_xor_sync(0xffffffffu, rs1, off);
    }
    float inv0 = 1.f / rs0, inv1 = 1.f / rs1;
    size_t r0 = m0 + 16*w + g, r1 = r0 + 8;
    #pragma unroll
    for (int nt = 0; nt < 8; nt++) {
        size_t cc = nt*8 + 2*t4;
        *(unsigned*)&O[((size_t)(b*NL + r0)*NH + h)*64 + cc] =
            packbf(o_acc[nt][0]*inv0, o_acc[nt][1]*inv0);
        *(unsigned*)&O[((size_t)(b*NL + r1)*NH + h)*64 + cc] =
            packbf(o_acc[nt][2]*inv1, o_acc[nt][3]*inv1);
    }
}

// ---------------- launcher: round-10 graph + split wkv convert ----------------
static cudaStream_t g_s1 = nullptr, g_s2 = nullptr;
static cudaEvent_t  g_ev[8];

extern "C" void kernel_launch(void* const* d_in, const int* in_sizes, int n_in,
                              void* d_out, int out_size) {
    const float* x      = (const float*)d_in[0];
    const float* pos    = (const float*)d_in[1];
    const float* x_cross= (const float*)d_in[2];
    const float* posc   = (const float*)d_in[3];
    const float* nscale = (const float*)d_in[4];
    const float* ncscale= (const float*)d_in[5];
    const float* q_w    = (const float*)d_in[6];
    const float* kv_w   = (const float*)d_in[7];
    const float* hscale = (const float*)d_in[8];
    const float* out_w  = (const float*)d_in[9];
    float* out = (float*)d_out;

    if (!g_s1) {
        cudaStreamCreateWithFlags(&g_s1, cudaStreamNonBlocking);
        cudaStreamCreateWithFlags(&g_s2, cudaStreamNonBlocking);
        for (int i = 0; i < 8; i++)
            cudaEventCreateWithFlags(&g_ev[i], cudaEventDisableTiming);
    }
    cudaEvent_t eFork = g_ev[0], eFtab = g_ev[1], eXcb = g_ev[2], eWkvK = g_ev[3],
                eWkvV = g_ev[4], eWout = g_ev[5], eQ = g_ev[6], eV = g_ev[7];

    bf16 *xnb, *xcb, *wq, *wkv, *wout, *qpre, *kvb, *qb, *kb, *ob;
    cudaGetSymbolAddress((void**)&xnb, g_xnb);
    cudaGetSymbolAddress((void**)&xcb, g_xcb);
    cudaGetSymbolAddress((void**)&wq,  g_wq);
    cudaGetSymbolAddress((void**)&wkv, g_wkv);
    cudaGetSymbolAddress((void**)&wout,g_wout);
    cudaGetSymbolAddress((void**)&qpre,g_qpre);
    cudaGetSymbolAddress((void**)&kvb, g_kvb);
    cudaGetSymbolAddress((void**)&qb,  g_qb);
    cudaGetSymbolAddress((void**)&kb,  g_kb);
    cudaGetSymbolAddress((void**)&ob,  g_ob);

    cudaFuncSetAttribute(gemm_bf<bf16,false>, cudaFuncAttributeMaxDynamicSharedMemorySize, GEMM_SMEM);
    cudaFuncSetAttribute(gemm_bf<float,true>, cudaFuncAttributeMaxDynamicSharedMemorySize, GEMM_SMEM);
    cudaFuncSetAttribute(attn_bf16, cudaFuncAttributeMaxDynamicSharedMemorySize, ATT_SMEM);

    const dim3 gFull(8, NROWS/128);

    // fork
    cudaEventRecord(eFork, 0);
    cudaStreamWaitEvent(g_s1, eFork, 0);
    cudaStreamWaitEvent(g_s2, eFork, 0);

    // ---- s2: wkv K-half convert FIRST (gates critical-path K-proj), then the rest
    f2b_k<<<(DMODEL*DMODEL/4 + 255)/256, 256, 0, g_s2>>>(kv_w, wkv, DMODEL*DMODEL/4);
    cudaEventRecord(eWkvK, g_s2);
    f2b_k<<<(DMODEL*DMODEL/4 + 255)/256, 256, 0, g_s2>>>(
        kv_w + (size_t)DMODEL*DMODEL, wkv + (size_t)DMODEL*DMODEL, DMODEL*DMODEL/4);
    cudaEventRecord(eWkvV, g_s2);
    ftab_k<<<1, 160, 0, g_s2>>>();
    cudaEventRecord(eFtab, g_s2);
    f2b_k<<<(DMODEL*DMODEL/4 + 255)/256, 256, 0, g_s2>>>(out_w, wout, DMODEL*DMODEL/4);
    cudaEventRecord(eWout, g_s2);

    // ---- s1: q-side chain ----
    f2b_k<<<(DMODEL*DMODEL/4 + 255)/256, 256, 0, g_s1>>>(q_w, wq, DMODEL*DMODEL/4);
    rmsnorm_k<<<NROWS/8, 256, 0, g_s1>>>(x, nscale, xnb);
    gemm_bf<bf16,false><<<gFull, 256, GEMM_SMEM, g_s1>>>(
        xnb, wq, nullptr, qpre, NROWS, DMODEL, DMODEL);
    cudaStreamWaitEvent(g_s1, eFtab, 0);
    qkprep_k<<<NROWS*NH/16, 256, 0, g_s1>>>(qpre, DMODEL, pos, hscale, qb);
    cudaEventRecord(eQ, g_s1);

    // ---- s0 (critical path): rms_xc -> K-proj -> K-prep -> attn -> out-proj ----
    rmsnorm_k<<<NROWS/8, 256>>>(x_cross, ncscale, xcb);
    cudaEventRecord(eXcb, 0);

    // V projection on s2 (needs wkv V-half + xcb), overlaps with K chain on s0
    cudaStreamWaitEvent(g_s2, eXcb, 0);
    gemm_bf<bf16,false><<<gFull, 256, GEMM_SMEM, g_s2>>>(
        xcb, wkv + (size_t)DMODEL*DMODEL, nullptr, kvb + DMODEL, NROWS, DMODEL, 2*DMODEL);
    cudaEventRecord(eV, g_s2);

    // K projection + prep on s0 (needs only the K-half of wkv)
    cudaStreamWaitEvent(0, eWkvK, 0);
    gemm_bf<bf16,false><<<gFull, 256, GEMM_SMEM>>>(
        xcb, wkv, nullptr, kvb, NROWS, DMODEL, 2*DMODEL);
    cudaStreamWaitEvent(0, eFtab, 0);
    qkprep_k<<<NROWS*NH/16, 256>>>(kvb, 2*DMODEL, posc, hscale, kb);

    cudaStreamWaitEvent(0, eQ, 0);   // join q chain
    cudaStreamWaitEvent(0, eV, 0);   // join V projection
    attn_bf16<<<dim3(NL/128, NH, NB), 256, ATT_SMEM>>>(qb, kb, kvb, ob);

    cudaStreamWaitEvent(0, eWout, 0); // join wout convert
    gemm_bf<float,true><<<gFull, 256, GEMM_SMEM>>>(
        ob, wout, x, out, NROWS, DMODEL, DMODEL);
}